// round 11
// baseline (speedup 1.0000x reference)
#include <cuda_runtime.h>
#include <cuda_fp16.h>
#include <cstdint>

#define BATCH 8
#define LEN   512
#define DIM   768
#define MAXW  12
#define NSPAN (LEN * MAXW)          // 6144
#define MROWS (BATCH * LEN)         // 4096

// ---------------------------------------------------------------------------
// Scratch (static device arrays; no allocation allowed)
// ---------------------------------------------------------------------------
__device__ __half g_h[MROWS * DIM];          // fp16(h)
__device__ __half g_S[MROWS * DIM];          // fp16(relu(h@Ws+bs))
__device__ __half g_E[MROWS * DIM];          // fp16(relu(h@We+be))
// Weights [K][N] fp16: [0]=Ws, [1]=We, [2]=Wo_top, [3]=Wo_bot
__device__ __half g_W[4 * DIM * DIM];
__device__ float g_P[MROWS * DIM];
__device__ float g_Q[MROWS * DIM];

// ---------------------------------------------------------------------------
// Fused fp32 -> fp16 convert: blockIdx.y = 0:h, 1:Ws, 2:We, 3:Wo
// ---------------------------------------------------------------------------
__global__ void conv_all_kernel(const float* __restrict__ h,
                                const float* __restrict__ Ws,
                                const float* __restrict__ We,
                                const float* __restrict__ Wo)
{
    const int region = blockIdx.y;
    const int W4 = (DIM * DIM) / 4;   // 147456
    const float* src;
    __half* dst;
    int n4;
    switch (region) {
        case 0: src = h;  dst = g_h;                  n4 = (MROWS * DIM) / 4; break; // 786432
        case 1: src = Ws; dst = g_W;                  n4 = W4; break;
        case 2: src = We; dst = g_W + DIM * DIM;      n4 = W4; break;
        default: src = Wo; dst = g_W + 2 * DIM * DIM; n4 = 2 * W4; break;
    }
    int i = blockIdx.x * blockDim.x + threadIdx.x;
    if (i >= n4) return;
    float4 v = ((const float4*)src)[i];
    ((__half2*)dst)[i * 2 + 0] = __floats2half2_rn(v.x, v.y);
    ((__half2*)dst)[i * 2 + 1] = __floats2half2_rn(v.z, v.w);
}

// ---------------------------------------------------------------------------
// MMA / async-copy helpers (fp16)
// ---------------------------------------------------------------------------
__device__ __forceinline__ void ldsm_x4(uint32_t* r, uint32_t addr)
{
    asm volatile("ldmatrix.sync.aligned.m8n8.x4.shared.b16 {%0,%1,%2,%3}, [%4];"
                 : "=r"(r[0]), "=r"(r[1]), "=r"(r[2]), "=r"(r[3]) : "r"(addr));
}
__device__ __forceinline__ void ldsm_x4_t(uint32_t* r, uint32_t addr)
{
    asm volatile("ldmatrix.sync.aligned.m8n8.x4.trans.shared.b16 {%0,%1,%2,%3}, [%4];"
                 : "=r"(r[0]), "=r"(r[1]), "=r"(r[2]), "=r"(r[3]) : "r"(addr));
}
__device__ __forceinline__ void mma_f16(float* c, const uint32_t* a, const uint32_t* b)
{
    asm volatile("mma.sync.aligned.m16n8k16.row.col.f32.f16.f16.f32 "
                 "{%0,%1,%2,%3}, {%4,%5,%6,%7}, {%8,%9}, {%0,%1,%2,%3};"
                 : "+f"(c[0]), "+f"(c[1]), "+f"(c[2]), "+f"(c[3])
                 : "r"(a[0]), "r"(a[1]), "r"(a[2]), "r"(a[3]), "r"(b[0]), "r"(b[1]));
}
__device__ __forceinline__ void cp16(uint32_t saddr, const void* gaddr)
{
    asm volatile("cp.async.cg.shared.global [%0], [%1], 16;" :: "r"(saddr), "l"(gaddr));
}
__device__ __forceinline__ void cp_commit() { asm volatile("cp.async.commit_group;"); }
template <int N> __device__ __forceinline__ void cp_wait()
{
    asm volatile("cp.async.wait_group %0;" :: "n"(N));
}

// ---------------------------------------------------------------------------
// Single-term fp16 tensor-core GEMM, 4-stage cp.async pipeline.
// C[M,N] = A[M,K] @ W[K,N], M=4096, N=768, K=768.
// BM=128, BN=64, BK=32. 128 threads = 4 warps (2m x 2n), warp tile 64x32.
// 3 CTAs/SM: grid 768/stage over 444 slots -> 86% wave utilization;
// 12 warps/SM for latency hiding.
// ---------------------------------------------------------------------------
#define ASTR 40                      // A smem row stride (elems)
#define BSTR 72                      // B smem row stride (elems)
#define A_BYTES (128 * ASTR * 2)     // 10240
#define B_BYTES (32 * BSTR * 2)      // 4608
#define STG_BYTES (A_BYTES + B_BYTES)       // 14848
#define NSTAGE 4
#define SMEM_TOTAL (NSTAGE * STG_BYTES)     // 59392
#define NIT (DIM / 32)               // 24

template <bool STAGE1>
__device__ __forceinline__ void gemm_body(
    const __half* __restrict__ A,
    const __half* __restrict__ W,
    const float* __restrict__ bias,
    __half* __restrict__ Oh,
    float* __restrict__ Of)
{
    extern __shared__ char smem[];
    const uint32_t smem_base = (uint32_t)__cvta_generic_to_shared(smem);

    const int tid  = threadIdx.x;          // 0..127
    const int lane = tid & 31;
    const int w    = tid >> 5;             // 0..3
    const int wm   = (w >> 1) * 64;        // warp m offset (0 or 64)
    const int wn   = (w & 1) * 32;         // warp n offset (0 or 32)
    const int bm   = blockIdx.y * 128;
    const int bn   = blockIdx.x * 64;

    // A: 512 16B-chunks, 4/thread: c = tid + i*128, row = c>>2, col = (c&3)*8
    // B: 256 16B-chunks, 2/thread: c = tid + i*128, row = c>>3, col = (c&7)*8
    auto issue_stage = [&](int stg, int k0) {
        const uint32_t sa = smem_base + stg * STG_BYTES;
        const uint32_t sb = sa + A_BYTES;
#pragma unroll
        for (int i = 0; i < 4; i++) {
            int c = tid + i * 128;
            int ar = c >> 2, ac = (c & 3) * 8;
            cp16(sa + ar * (ASTR * 2) + ac * 2,
                 A + (size_t)(bm + ar) * DIM + k0 + ac);
        }
#pragma unroll
        for (int i = 0; i < 2; i++) {
            int c = tid + i * 128;
            int br = c >> 3, bc2 = (c & 7) * 8;
            cp16(sb + br * (BSTR * 2) + bc2 * 2,
                 W + (size_t)(k0 + br) * DIM + bn + bc2);
        }
        cp_commit();
    };

    float acc[4][4][4];
#pragma unroll
    for (int i = 0; i < 4; i++)
#pragma unroll
        for (int j = 0; j < 4; j++)
#pragma unroll
            for (int k = 0; k < 4; k++) acc[i][j][k] = 0.0f;

    issue_stage(0, 0);
    issue_stage(1, 32);
    issue_stage(2, 64);

    for (int it = 0; it < NIT; it++) {
        cp_wait<2>();          // stage it%4 has landed (2 newer may fly)
        __syncthreads();       // all warps done with iter it-1 -> slot (it+3)%4 free

        if (it + 3 < NIT) issue_stage((it + 3) % NSTAGE, (it + 3) * 32);

        const int stg = it % NSTAGE;
        const uint32_t sa = smem_base + stg * STG_BYTES;
        const uint32_t sb = sa + A_BYTES;

#pragma unroll
        for (int kk = 0; kk < 32; kk += 16) {
            uint32_t af[4][4], bf[4][2];
#pragma unroll
            for (int mi = 0; mi < 4; mi++) {
                uint32_t off = (wm + mi * 16 + (lane & 15)) * (ASTR * 2)
                             + (kk + (lane >> 4) * 8) * 2;
                ldsm_x4(af[mi], sa + off);
            }
#pragma unroll
            for (int ni = 0; ni < 2; ni++) {
                uint32_t off = (kk + (lane & 15)) * (BSTR * 2)
                             + (wn + ni * 16 + (lane >> 4) * 8) * 2;
                uint32_t rb[4];
                ldsm_x4_t(rb, sb + off);
                bf[ni * 2][0] = rb[0]; bf[ni * 2][1] = rb[1];
                bf[ni * 2 + 1][0] = rb[2]; bf[ni * 2 + 1][1] = rb[3];
            }
#pragma unroll
            for (int mi = 0; mi < 4; mi++)
#pragma unroll
                for (int nj = 0; nj < 4; nj++)
                    mma_f16(acc[mi][nj], af[mi], bf[nj]);
        }
    }

    // Epilogue. c-frag: c0,c1 -> (row=lane>>2, col=(lane&3)*2+{0,1}); c2,c3 -> row+8.
    const int er = lane >> 2;
    const int ec = (lane & 3) * 2;
#pragma unroll
    for (int mi = 0; mi < 4; mi++) {
#pragma unroll
        for (int nj = 0; nj < 4; nj++) {
            int m0 = bm + wm + mi * 16 + er;
            int n0 = bn + wn + nj * 8 + ec;
            float v0 = acc[mi][nj][0], v1 = acc[mi][nj][1];
            float v2 = acc[mi][nj][2], v3 = acc[mi][nj][3];
            if (STAGE1) {
                float b0 = bias[n0], b1 = bias[n0 + 1];
                v0 = fmaxf(v0 + b0, 0.0f); v1 = fmaxf(v1 + b1, 0.0f);
                v2 = fmaxf(v2 + b0, 0.0f); v3 = fmaxf(v3 + b1, 0.0f);
                *(__half2*)&Oh[(size_t)m0 * DIM + n0]       = __floats2half2_rn(v0, v1);
                *(__half2*)&Oh[(size_t)(m0 + 8) * DIM + n0] = __floats2half2_rn(v2, v3);
            } else {
                *(float2*)&Of[(size_t)m0 * DIM + n0]       = make_float2(v0, v1);
                *(float2*)&Of[(size_t)(m0 + 8) * DIM + n0] = make_float2(v2, v3);
            }
        }
    }
}

__global__ __launch_bounds__(128, 3)
void stage1_kernel(const float* __restrict__ bs, const float* __restrict__ be)
{
    if (blockIdx.z == 0)
        gemm_body<true>(g_h, g_W, bs, g_S, nullptr);
    else
        gemm_body<true>(g_h, g_W + DIM * DIM, be, g_E, nullptr);
}

__global__ __launch_bounds__(128, 3)
void stage2_kernel()
{
    if (blockIdx.z == 0)
        gemm_body<false>(g_S, g_W + 2 * DIM * DIM, nullptr, nullptr, g_P);
    else
        gemm_body<false>(g_E, g_W + 3 * DIM * DIM, nullptr, nullptr, g_Q);
}

// ---------------------------------------------------------------------------
// Gather-add: out[b,n,:] = P[b, idx_s] + Q[b, idx_e] + bo   (span_idx int32)
// 4 rows per thread (8 independent gathered loads), streaming stores.
// ---------------------------------------------------------------------------
__global__ void gather_add_kernel(const int* __restrict__ span_idx,
                                  const float* __restrict__ bo,
                                  float* __restrict__ out)
{
    const int base = blockIdx.x * 16;
    const int ty = threadIdx.y;                 // 0..3
    const int t  = threadIdx.x;                 // 0..191
    float4 bv = __ldg(&((const float4*)bo)[t]);

    int   rows[4];
    const float4* pp[4];
    const float4* qq[4];
#pragma unroll
    for (int j = 0; j < 4; j++) {
        int r = base + j * 4 + ty;
        int b = r / NSPAN;
        int is = span_idx[r * 2], ie = span_idx[r * 2 + 1];
        rows[j] = r;
        pp[j] = (const float4*)(g_P + (size_t)(b * LEN + is) * DIM);
        qq[j] = (const float4*)(g_Q + (size_t)(b * LEN + ie) * DIM);
    }
    float4 pv[4], qv[4];
#pragma unroll
    for (int j = 0; j < 4; j++) pv[j] = pp[j][t];
#pragma unroll
    for (int j = 0; j < 4; j++) qv[j] = qq[j][t];
#pragma unroll
    for (int j = 0; j < 4; j++) {
        float4 o = make_float4(pv[j].x + qv[j].x + bv.x,
                               pv[j].y + qv[j].y + bv.y,
                               pv[j].z + qv[j].z + bv.z,
                               pv[j].w + qv[j].w + bv.w);
        __stcs(&((float4*)(out + (size_t)rows[j] * DIM))[t], o);
    }
}

extern "C" void kernel_launch(void* const* d_in, const int* in_sizes, int n_in,
                              void* d_out, int out_size)
{
    (void)in_sizes; (void)n_in; (void)out_size;
    const float* h    = (const float*)d_in[0];
    const int*   span = (const int*)d_in[1];
    const float* Ws   = (const float*)d_in[2];
    const float* bs   = (const float*)d_in[3];
    const float* We   = (const float*)d_in[4];
    const float* be   = (const float*)d_in[5];
    const float* Wo   = (const float*)d_in[6];
    const float* bo   = (const float*)d_in[7];
    float* out = (float*)d_out;

    static int smem_set = 0;
    if (!smem_set) {
        cudaFuncSetAttribute(stage1_kernel,
                             cudaFuncAttributeMaxDynamicSharedMemorySize, SMEM_TOTAL);
        cudaFuncSetAttribute(stage2_kernel,
                             cudaFuncAttributeMaxDynamicSharedMemorySize, SMEM_TOTAL);
        smem_set = 1;
    }

    conv_all_kernel<<<dim3(3072, 4), 256>>>(h, Ws, We, Wo);

    dim3 gemm_grid(DIM / 64, MROWS / 128, 2);          // (12, 32, 2) = 768
    stage1_kernel<<<gemm_grid, 128, SMEM_TOTAL>>>(bs, be);
    stage2_kernel<<<gemm_grid, 128, SMEM_TOTAL>>>();

    dim3 gblock(192, 4);
    gather_add_kernel<<<(BATCH * NSPAN) / 16, gblock>>>(span, bo, out);
}